// round 3
// baseline (speedup 1.0000x reference)
#include <cuda_runtime.h>
#include <cstdint>
#include <cstddef>

#define TOPK 13
#define MAX_P 90112
#define MAX_G 128

// Scratch (allocation-free: __device__ globals)
__device__ unsigned long long g_key[MAX_P];   // packed (align_bits<<32)|(0x7FFFFFFF-g)
__device__ int g_labels[MAX_G];
__device__ int g_valid[MAX_G];
__device__ int g_analytic;                    // 1 if anchor grid matches known structure

// Known grid structure (IMG=2048, strides 8/16/32): verified at runtime.
#define L0N 256
#define L1N 128
#define L2N 64
#define L0B 0
#define L1B 65536
#define L2B 81920
#define P_EXPECT 86016

// ---------------------------------------------------------------------------
// Kernel 1: zero target_scores region of d_out (P*C floats) + zero g_key +
// decode gt_labels / valid mask + detect anchor-grid structure.
// ---------------------------------------------------------------------------
__global__ void zero_and_decode(float* __restrict__ out,
                                const void* labels_raw, const unsigned char* mask_raw,
                                const float* __restrict__ anchors,
                                int P, int G, int C) {
    size_t nscore = (size_t)P * (size_t)C;
    size_t n4 = nscore >> 2;
    size_t tid = (size_t)blockIdx.x * blockDim.x + threadIdx.x;
    size_t stride = (size_t)gridDim.x * blockDim.x;
    float4 z4 = make_float4(0.f, 0.f, 0.f, 0.f);
    for (size_t i = tid; i < n4; i += stride) ((float4*)out)[i] = z4;
    for (size_t i = (n4 << 2) + tid; i < nscore; i += stride) out[i] = 0.f;
    for (size_t i = tid; i < (size_t)P; i += stride) g_key[i] = 0ull;

    if (blockIdx.x == 0 && threadIdx.x == 0) {
        // labels dtype sniff: int64 labels < C -> odd 32-bit words all zero.
        const int* as32 = (const int*)labels_raw;
        bool is64 = true;
        for (int j = 1; j < G; j += 2) {
            if (as32[j] != 0) { is64 = false; break; }
        }
        // mask dtype sniff: u8 bool mask (all true) -> first 4 bytes nonzero.
        const unsigned char* m = mask_raw;
        bool mask_u8 = (m[0] != 0) && (m[1] != 0) && (m[2] != 0) && (m[3] != 0);
        const int* mi = (const int*)mask_raw;
        for (int g = 0; g < G; g++) {
            long long lab = is64 ? ((const long long*)labels_raw)[g] : (long long)as32[g];
            int li = (int)lab;
            int cl = li < 0 ? 0 : (li >= C ? C - 1 : li);
            g_labels[g] = cl;
            int mv = mask_u8 ? (m[cl] != 0) : (mi[cl] != 0);
            g_valid[g] = (li >= 0 && li < C && mv) ? 1 : 0;
        }
        // anchor-grid structure check ((i+0.5)*s is exact in fp32)
        int ok = (P == P_EXPECT)
              && anchors[0] == 4.0f && anchors[1] == 4.0f
              && anchors[2] == 12.0f
              && anchors[2 * 65535] == 2044.0f && anchors[2 * 65535 + 1] == 2044.0f
              && anchors[2 * L1B] == 8.0f && anchors[2 * L1B + 1] == 8.0f
              && anchors[2 * L2B] == 16.0f && anchors[2 * L2B + 1] == 16.0f
              && anchors[2 * (P_EXPECT - 1)] == 2032.0f
              && anchors[2 * (P_EXPECT - 1) + 1] == 2032.0f;
        g_analytic = ok;
    }
}

// Conservative cell range: centers (i+0.5)*s possibly in [lo,hi], widened by
// 1 cell each side to absorb division rounding; exact predicate applied later.
__device__ __forceinline__ void cell_range_cons(float lo, float hi, float s, int n,
                                                int& i0, int& i1) {
    i0 = (int)floorf(lo / s - 0.5f) - 1;
    i1 = (int)ceilf(hi / s - 0.5f) + 1;
    if (i0 < 0) i0 = 0;
    if (i1 > n - 1) i1 = n - 1;
}

// ---------------------------------------------------------------------------
// Kernel 2: one block per GT. Analytic path: iterate only the conservative
// inside-rect per pyramid level (~2k cells vs 86k anchors), applying the
// reference's EXACT predicates per anchor. Pass A: has_center (block OR).
// Pass B: align on candidates, per-thread sorted top-13 packed keys,
// shared-memory tree merge, atomicMax scatter.
// Key: (float_bits(align)<<32)|(0x7FFFFFFF-anchor_idx); align>=0 so float
// bits are order-preserving; ties -> lower anchor idx; key==0 <=> empty.
// ---------------------------------------------------------------------------
__global__ void __launch_bounds__(256) topk_per_gt(
    const float* __restrict__ scores, const float* __restrict__ pboxes,
    const float* __restrict__ obj, const float* __restrict__ anchors,
    const float* __restrict__ gboxes, int P, int C) {
    int g = blockIdx.x;
    int tid = threadIdx.x;
    if (!g_valid[g]) return;  // uniform per block

    float x0 = gboxes[4 * g + 0], y0 = gboxes[4 * g + 1];
    float x1 = gboxes[4 * g + 2], y1 = gboxes[4 * g + 3];
    float cx = (x0 + x1) * 0.5f, cy = (y0 + y1) * 0.5f;
    float hx = fmaxf((x1 - x0) * 0.5f, 1.0f);
    float hy = fmaxf((y1 - y0) * 0.5f, 1.0f);
    float area_g = fmaxf(x1 - x0, 0.f) * fmaxf(y1 - y0, 0.f);
    int label = g_labels[g];

    unsigned long long lk[TOPK];
#pragma unroll
    for (int j = 0; j < TOPK; j++) lk[j] = 0ull;

    __shared__ int s_any;
    if (tid == 0) s_any = 0;
    __syncthreads();

    if (g_analytic) {
        const float SS[3] = {8.f, 16.f, 32.f};
        const int   NN[3] = {L0N, L1N, L2N};
        const int   BB[3] = {L0B, L1B, L2B};

        int ix0[3], nx[3], iy0[3], cnt[3];
        int total = 0;
#pragma unroll
        for (int l = 0; l < 3; l++) {
            int a0, a1, b0, b1;
            cell_range_cons(x0, x1, SS[l], NN[l], a0, a1);
            cell_range_cons(y0, y1, SS[l], NN[l], b0, b1);
            ix0[l] = a0; nx[l] = (a1 >= a0) ? (a1 - a0 + 1) : 0;
            iy0[l] = b0;
            int nyl = (b1 >= b0) ? (b1 - b0 + 1) : 0;
            cnt[l] = nx[l] * nyl;
            total += cnt[l];
        }

        // ---- pass A: has_center (exact predicate over the rect) ----
        int anyl = 0;
        for (int j = tid; j < total; j += 256) {
            int l = 0, jj = j;
            if (jj >= cnt[0]) { jj -= cnt[0]; l = 1; }
            if (l == 1 && jj >= cnt[1]) { jj -= cnt[1]; l = 2; }
            int iy = iy0[l] + jj / nx[l];
            int ix = ix0[l] + jj % nx[l];
            float s = SS[l];
            float axp = ((float)ix + 0.5f) * s;
            float ayp = ((float)iy + 0.5f) * s;
            if (axp >= x0 && axp <= x1 && ayp >= y0 && ayp <= y1) {
                float dx = fabsf(axp - cx) / hx;
                float dy = fabsf(ayp - cy) / hy;
                if (fmaxf(dx, dy) <= 0.5f) { anyl = 1; break; }
            }
        }
        if (anyl) s_any = 1;     // benign race, same value
        __syncthreads();
        bool strict_mode = (s_any != 0);

        // ---- pass B: align + top-13 on candidates ----
        for (int j = tid; j < total; j += 256) {
            int l = 0, jj = j;
            if (jj >= cnt[0]) { jj -= cnt[0]; l = 1; }
            if (l == 1 && jj >= cnt[1]) { jj -= cnt[1]; l = 2; }
            int iy = iy0[l] + jj / nx[l];
            int ix = ix0[l] + jj % nx[l];
            int p = BB[l] + iy * NN[l] + ix;
            float s = SS[l];
            float axp = ((float)ix + 0.5f) * s;
            float ayp = ((float)iy + 0.5f) * s;

            if (!(axp >= x0 && axp <= x1 && ayp >= y0 && ayp <= y1)) continue;
            float dx = fabsf(axp - cx) / hx;
            float dy = fabsf(ayp - cy) / hy;
            if (strict_mode && fmaxf(dx, dy) > 0.5f) continue;

            float4 pb = ((const float4*)pboxes)[p];
            float iix0 = fmaxf(x0, pb.x), iiy0 = fmaxf(y0, pb.y);
            float iix1 = fminf(x1, pb.z), iiy1 = fminf(y1, pb.w);
            float inter = fmaxf(iix1 - iix0, 0.f) * fmaxf(iiy1 - iiy0, 0.f);
            float area_p = fmaxf(pb.z - pb.x, 0.f) * fmaxf(pb.w - pb.y, 0.f);
            float iou = inter / (area_g + area_p - inter + 1e-7f);

            float sv = scores[(size_t)p * C + label];
            float cls = 1.f / (1.f + expf(-sv));
            float ob = 1.f / (1.f + expf(-obj[p]));
            float quality = sqrtf(fmaxf(ob * cls, 0.f));
            float prior = expf(-0.5f * (dx * dx + dy * dy));
            float iou2 = iou * iou;
            float align = quality * (iou2 * iou2 * iou2) * prior;

            unsigned long long k =
                ((unsigned long long)__float_as_uint(align) << 32) |
                (unsigned long long)(0x7FFFFFFFu - (unsigned)p);
            if (k > lk[TOPK - 1]) {
                int q = TOPK - 1;
                while (q > 0 && lk[q - 1] < k) { lk[q] = lk[q - 1]; --q; }
                lk[q] = k;
            }
        }
    } else {
        // ---- generic fallback: full scan over all anchors ----
        int anyl = 0;
        for (int p = tid; p < P; p += 256) {
            float2 a = ((const float2*)anchors)[p];
            if (a.x >= x0 && a.x <= x1 && a.y >= y0 && a.y <= y1) {
                float dx = fabsf(a.x - cx) / hx;
                float dy = fabsf(a.y - cy) / hy;
                if (fmaxf(dx, dy) <= 0.5f) { anyl = 1; break; }
            }
        }
        if (anyl) s_any = 1;
        __syncthreads();
        bool strict_mode = (s_any != 0);

        for (int p = tid; p < P; p += 256) {
            float2 a = ((const float2*)anchors)[p];
            if (!(a.x >= x0 && a.x <= x1 && a.y >= y0 && a.y <= y1)) continue;
            float dx = fabsf(a.x - cx) / hx;
            float dy = fabsf(a.y - cy) / hy;
            if (strict_mode && fmaxf(dx, dy) > 0.5f) continue;

            float4 pb = ((const float4*)pboxes)[p];
            float iix0 = fmaxf(x0, pb.x), iiy0 = fmaxf(y0, pb.y);
            float iix1 = fminf(x1, pb.z), iiy1 = fminf(y1, pb.w);
            float inter = fmaxf(iix1 - iix0, 0.f) * fmaxf(iiy1 - iiy0, 0.f);
            float area_p = fmaxf(pb.z - pb.x, 0.f) * fmaxf(pb.w - pb.y, 0.f);
            float iou = inter / (area_g + area_p - inter + 1e-7f);

            float sv = scores[(size_t)p * C + label];
            float cls = 1.f / (1.f + expf(-sv));
            float ob = 1.f / (1.f + expf(-obj[p]));
            float quality = sqrtf(fmaxf(ob * cls, 0.f));
            float prior = expf(-0.5f * (dx * dx + dy * dy));
            float iou2 = iou * iou;
            float align = quality * (iou2 * iou2 * iou2) * prior;

            unsigned long long k =
                ((unsigned long long)__float_as_uint(align) << 32) |
                (unsigned long long)(0x7FFFFFFFu - (unsigned)p);
            if (k > lk[TOPK - 1]) {
                int q = TOPK - 1;
                while (q > 0 && lk[q - 1] < k) { lk[q] = lk[q - 1]; --q; }
                lk[q] = k;
            }
        }
    }

    // ---- tree merge in shared memory ----
    __shared__ unsigned long long sm[256 * TOPK];
#pragma unroll
    for (int j = 0; j < TOPK; j++) sm[tid * TOPK + j] = lk[j];
    __syncthreads();

    for (int stride = 128; stride > 0; stride >>= 1) {
        if (tid < stride) {
            unsigned long long* A = &sm[tid * TOPK];
            const unsigned long long* B = &sm[(tid + stride) * TOPK];
            unsigned long long outv[TOPK];
            int ia = 0, ib = 0;
#pragma unroll
            for (int j = 0; j < TOPK; j++) {
                unsigned long long av = (ia < TOPK) ? A[ia] : 0ull;
                unsigned long long bv = (ib < TOPK) ? B[ib] : 0ull;
                if (av >= bv) { outv[j] = av; ia++; }
                else          { outv[j] = bv; ib++; }
            }
#pragma unroll
            for (int j = 0; j < TOPK; j++) A[j] = outv[j];
        }
        __syncthreads();
    }

    // ---- scatter selected anchors (<=13) ----
    if (tid < TOPK) {
        unsigned long long k = sm[tid];
        if (k != 0ull) {
            unsigned p = 0x7FFFFFFFu - (unsigned)(k & 0xFFFFFFFFu);
            unsigned long long nk = (k & 0xFFFFFFFF00000000ull) |
                                    (unsigned long long)(0x7FFFFFFFu - (unsigned)g);
            atomicMax(&g_key[p], nk);
        }
    }
}

// ---------------------------------------------------------------------------
// Kernel 3: per-anchor finalize. g_key==0 <=> background (selections always
// have nonzero low word). Recompute IoU for the winning GT only.
// Output layout (float32, reference return order, flattened):
//   [0, P*C) target_scores | next 4P target_boxes | next P fg_mask
//   | next P matched_gt_indices | next P matched_labels
// ---------------------------------------------------------------------------
__global__ void finalize(const float* __restrict__ pboxes,
                         const float* __restrict__ gboxes,
                         float* __restrict__ out, int P, int C) {
    int p = blockIdx.x * blockDim.x + threadIdx.x;
    if (p >= P) return;
    float* out_boxes = out + (size_t)P * C;
    float* out_fg = out_boxes + (size_t)P * 4;
    float* out_mgi = out_fg + P;
    float* out_ml = out_mgi + P;

    unsigned long long k = g_key[p];
    if (k != 0ull) {
        int g = (int)(0x7FFFFFFFu - (unsigned)(k & 0xFFFFFFFFu));
        float x0 = gboxes[4 * g + 0], y0 = gboxes[4 * g + 1];
        float x1 = gboxes[4 * g + 2], y1 = gboxes[4 * g + 3];
        float4 pb = ((const float4*)pboxes)[p];
        float ix0 = fmaxf(x0, pb.x), iy0 = fmaxf(y0, pb.y);
        float ix1 = fminf(x1, pb.z), iy1 = fminf(y1, pb.w);
        float inter = fmaxf(ix1 - ix0, 0.f) * fmaxf(iy1 - iy0, 0.f);
        float ag = fmaxf(x1 - x0, 0.f) * fmaxf(y1 - y0, 0.f);
        float ap = fmaxf(pb.z - pb.x, 0.f) * fmaxf(pb.w - pb.y, 0.f);
        float iou = inter / (ag + ap - inter + 1e-7f);
        int label = g_labels[g];

        ((float4*)out_boxes)[p] = make_float4(x0, y0, x1, y1);
        out_fg[p] = 1.0f;
        out_mgi[p] = (float)g;
        out_ml[p] = (float)label;
        out[(size_t)p * C + label] = fmaxf(iou, 0.1f);
    } else {
        ((float4*)out_boxes)[p] = make_float4(0.f, 0.f, 0.f, 0.f);
        out_fg[p] = 0.f;
        out_mgi[p] = -1.f;
        out_ml[p] = -1.f;
    }
}

// ---------------------------------------------------------------------------
extern "C" void kernel_launch(void* const* d_in, const int* in_sizes, int n_in,
                              void* d_out, int out_size) {
    const float* pred_scores = (const float*)d_in[0];
    const float* pred_boxes  = (const float*)d_in[1];
    const float* pred_obj    = (const float*)d_in[2];
    const float* anchors     = (const float*)d_in[3];
    const float* gt_boxes    = (const float*)d_in[4];
    const void*  gt_labels   = d_in[5];
    const unsigned char* vmask = (const unsigned char*)d_in[6];

    int P = in_sizes[2];            // pred_objectness count
    int C = in_sizes[0] / P;        // pred_scores is (P, C)
    int G = in_sizes[4] / 4;        // gt_boxes is (G, 4)

    zero_and_decode<<<4096, 256>>>((float*)d_out, gt_labels, vmask, anchors, P, G, C);
    topk_per_gt<<<G, 256>>>(pred_scores, pred_boxes, pred_obj, anchors, gt_boxes, P, C);
    finalize<<<(P + 255) / 256, 256>>>(pred_boxes, gt_boxes, (float*)d_out, P, C);
}

// round 4
// speedup vs baseline: 1.1772x; 1.1772x over previous
#include <cuda_runtime.h>
#include <cstdint>
#include <cstddef>

#define TOPK 13
#define MAX_P 90112
#define MAX_G 128

// Scratch (allocation-free: __device__ globals)
__device__ unsigned long long g_key[MAX_P];   // packed (align_bits<<32)|(0x7FFFFFFF-g)
__device__ int g_labels[MAX_G];
__device__ int g_valid[MAX_G];
__device__ int g_analytic;                    // 1 if anchor grid matches known structure

// Known grid structure (IMG=2048, strides 8/16/32): verified at runtime.
#define L0N 256
#define L1N 128
#define L2N 64
#define L0B 0
#define L1B 65536
#define L2B 81920
#define P_EXPECT 86016

// ---------------------------------------------------------------------------
// Kernel 1: parallel decode of gt_labels / valid mask (one thread per GT,
// broadcast-load dtype sniff) + zero g_key + anchor-grid structure check.
// No serial tail: every step is warp-parallel over cached data.
// ---------------------------------------------------------------------------
__global__ void decode_and_zerokey(const void* labels_raw, const unsigned char* mask_raw,
                                   const float* __restrict__ anchors,
                                   int P, int G, int C) {
    int tid = blockIdx.x * blockDim.x + threadIdx.x;
    int stride = gridDim.x * blockDim.x;
    for (int i = tid; i < P; i += stride) g_key[i] = 0ull;

    if (tid < G) {
        // labels dtype sniff: int64 labels < C -> odd 32-bit words all zero.
        // All threads scan the same words (broadcast loads, L1/L2 hits).
        const int* as32 = (const int*)labels_raw;
        bool is64 = true;
        for (int j = 1; j < G; j += 2) {
            if (as32[j] != 0) { is64 = false; break; }
        }
        const unsigned char* m = mask_raw;
        bool mask_u8 = (m[0] != 0) && (m[1] != 0) && (m[2] != 0) && (m[3] != 0);
        const int* mi = (const int*)mask_raw;

        int g = tid;
        long long lab = is64 ? ((const long long*)labels_raw)[g] : (long long)as32[g];
        int li = (int)lab;
        int cl = li < 0 ? 0 : (li >= C ? C - 1 : li);
        g_labels[g] = cl;
        int mv = mask_u8 ? (m[cl] != 0) : (mi[cl] != 0);
        g_valid[g] = (li >= 0 && li < C && mv) ? 1 : 0;
    }
    if (tid == 0) {
        // anchor-grid structure check ((i+0.5)*s is exact in fp32)
        int ok = (P == P_EXPECT)
              && anchors[0] == 4.0f && anchors[1] == 4.0f
              && anchors[2] == 12.0f
              && anchors[2 * 65535] == 2044.0f && anchors[2 * 65535 + 1] == 2044.0f
              && anchors[2 * L1B] == 8.0f && anchors[2 * L1B + 1] == 8.0f
              && anchors[2 * L2B] == 16.0f && anchors[2 * L2B + 1] == 16.0f
              && anchors[2 * (P_EXPECT - 1)] == 2032.0f
              && anchors[2 * (P_EXPECT - 1) + 1] == 2032.0f;
        g_analytic = ok;
    }
}

// Conservative cell range: centers (i+0.5)*s possibly in [lo,hi], widened by
// 1 cell each side to absorb division rounding; exact predicate applied later.
__device__ __forceinline__ void cell_range_cons(float lo, float hi, float s, int n,
                                                int& i0, int& i1) {
    i0 = (int)floorf(lo / s - 0.5f) - 1;
    i1 = (int)ceilf(hi / s - 0.5f) + 1;
    if (i0 < 0) i0 = 0;
    if (i1 > n - 1) i1 = n - 1;
}

// ---------------------------------------------------------------------------
// Kernel 2: one block per GT. Analytic path: iterate only the conservative
// inside-rect per pyramid level (~2k cells vs 86k anchors), applying the
// reference's EXACT predicates per anchor. Pass A: has_center (block OR).
// Pass B: align on candidates, per-thread sorted top-13 packed keys,
// shared-memory tree merge, atomicMax scatter.
// Key: (float_bits(align)<<32)|(0x7FFFFFFF-anchor_idx); align>=0 so float
// bits are order-preserving; ties -> lower anchor idx; key==0 <=> empty.
// ---------------------------------------------------------------------------
__global__ void __launch_bounds__(256) topk_per_gt(
    const float* __restrict__ scores, const float* __restrict__ pboxes,
    const float* __restrict__ obj, const float* __restrict__ anchors,
    const float* __restrict__ gboxes, int P, int C) {
    int g = blockIdx.x;
    int tid = threadIdx.x;
    if (!g_valid[g]) return;  // uniform per block

    float x0 = gboxes[4 * g + 0], y0 = gboxes[4 * g + 1];
    float x1 = gboxes[4 * g + 2], y1 = gboxes[4 * g + 3];
    float cx = (x0 + x1) * 0.5f, cy = (y0 + y1) * 0.5f;
    float hx = fmaxf((x1 - x0) * 0.5f, 1.0f);
    float hy = fmaxf((y1 - y0) * 0.5f, 1.0f);
    float area_g = fmaxf(x1 - x0, 0.f) * fmaxf(y1 - y0, 0.f);
    int label = g_labels[g];

    unsigned long long lk[TOPK];
#pragma unroll
    for (int j = 0; j < TOPK; j++) lk[j] = 0ull;

    __shared__ int s_any;
    if (tid == 0) s_any = 0;
    __syncthreads();

    if (g_analytic) {
        const float SS[3] = {8.f, 16.f, 32.f};
        const int   NN[3] = {L0N, L1N, L2N};
        const int   BB[3] = {L0B, L1B, L2B};

        int ix0[3], nx[3], iy0[3], cnt[3];
        int total = 0;
#pragma unroll
        for (int l = 0; l < 3; l++) {
            int a0, a1, b0, b1;
            cell_range_cons(x0, x1, SS[l], NN[l], a0, a1);
            cell_range_cons(y0, y1, SS[l], NN[l], b0, b1);
            ix0[l] = a0; nx[l] = (a1 >= a0) ? (a1 - a0 + 1) : 0;
            iy0[l] = b0;
            int nyl = (b1 >= b0) ? (b1 - b0 + 1) : 0;
            cnt[l] = nx[l] * nyl;
            total += cnt[l];
        }

        // ---- pass A: has_center (exact predicate over the rect) ----
        int anyl = 0;
        for (int j = tid; j < total; j += 256) {
            int l = 0, jj = j;
            if (jj >= cnt[0]) { jj -= cnt[0]; l = 1; }
            if (l == 1 && jj >= cnt[1]) { jj -= cnt[1]; l = 2; }
            int iy = iy0[l] + jj / nx[l];
            int ix = ix0[l] + jj % nx[l];
            float s = SS[l];
            float axp = ((float)ix + 0.5f) * s;
            float ayp = ((float)iy + 0.5f) * s;
            if (axp >= x0 && axp <= x1 && ayp >= y0 && ayp <= y1) {
                float dx = fabsf(axp - cx) / hx;
                float dy = fabsf(ayp - cy) / hy;
                if (fmaxf(dx, dy) <= 0.5f) { anyl = 1; break; }
            }
        }
        if (anyl) s_any = 1;     // benign race, same value
        __syncthreads();
        bool strict_mode = (s_any != 0);

        // ---- pass B: align + top-13 on candidates ----
        for (int j = tid; j < total; j += 256) {
            int l = 0, jj = j;
            if (jj >= cnt[0]) { jj -= cnt[0]; l = 1; }
            if (l == 1 && jj >= cnt[1]) { jj -= cnt[1]; l = 2; }
            int iy = iy0[l] + jj / nx[l];
            int ix = ix0[l] + jj % nx[l];
            int p = BB[l] + iy * NN[l] + ix;
            float s = SS[l];
            float axp = ((float)ix + 0.5f) * s;
            float ayp = ((float)iy + 0.5f) * s;

            if (!(axp >= x0 && axp <= x1 && ayp >= y0 && ayp <= y1)) continue;
            float dx = fabsf(axp - cx) / hx;
            float dy = fabsf(ayp - cy) / hy;
            if (strict_mode && fmaxf(dx, dy) > 0.5f) continue;

            float4 pb = ((const float4*)pboxes)[p];
            float iix0 = fmaxf(x0, pb.x), iiy0 = fmaxf(y0, pb.y);
            float iix1 = fminf(x1, pb.z), iiy1 = fminf(y1, pb.w);
            float inter = fmaxf(iix1 - iix0, 0.f) * fmaxf(iiy1 - iiy0, 0.f);
            float area_p = fmaxf(pb.z - pb.x, 0.f) * fmaxf(pb.w - pb.y, 0.f);
            float iou = inter / (area_g + area_p - inter + 1e-7f);

            float sv = scores[(size_t)p * C + label];
            float cls = 1.f / (1.f + expf(-sv));
            float ob = 1.f / (1.f + expf(-obj[p]));
            float quality = sqrtf(fmaxf(ob * cls, 0.f));
            float prior = expf(-0.5f * (dx * dx + dy * dy));
            float iou2 = iou * iou;
            float align = quality * (iou2 * iou2 * iou2) * prior;

            unsigned long long k =
                ((unsigned long long)__float_as_uint(align) << 32) |
                (unsigned long long)(0x7FFFFFFFu - (unsigned)p);
            if (k > lk[TOPK - 1]) {
                int q = TOPK - 1;
                while (q > 0 && lk[q - 1] < k) { lk[q] = lk[q - 1]; --q; }
                lk[q] = k;
            }
        }
    } else {
        // ---- generic fallback: full scan over all anchors ----
        int anyl = 0;
        for (int p = tid; p < P; p += 256) {
            float2 a = ((const float2*)anchors)[p];
            if (a.x >= x0 && a.x <= x1 && a.y >= y0 && a.y <= y1) {
                float dx = fabsf(a.x - cx) / hx;
                float dy = fabsf(a.y - cy) / hy;
                if (fmaxf(dx, dy) <= 0.5f) { anyl = 1; break; }
            }
        }
        if (anyl) s_any = 1;
        __syncthreads();
        bool strict_mode = (s_any != 0);

        for (int p = tid; p < P; p += 256) {
            float2 a = ((const float2*)anchors)[p];
            if (!(a.x >= x0 && a.x <= x1 && a.y >= y0 && a.y <= y1)) continue;
            float dx = fabsf(a.x - cx) / hx;
            float dy = fabsf(a.y - cy) / hy;
            if (strict_mode && fmaxf(dx, dy) > 0.5f) continue;

            float4 pb = ((const float4*)pboxes)[p];
            float iix0 = fmaxf(x0, pb.x), iiy0 = fmaxf(y0, pb.y);
            float iix1 = fminf(x1, pb.z), iiy1 = fminf(y1, pb.w);
            float inter = fmaxf(iix1 - iix0, 0.f) * fmaxf(iiy1 - iiy0, 0.f);
            float area_p = fmaxf(pb.z - pb.x, 0.f) * fmaxf(pb.w - pb.y, 0.f);
            float iou = inter / (area_g + area_p - inter + 1e-7f);

            float sv = scores[(size_t)p * C + label];
            float cls = 1.f / (1.f + expf(-sv));
            float ob = 1.f / (1.f + expf(-obj[p]));
            float quality = sqrtf(fmaxf(ob * cls, 0.f));
            float prior = expf(-0.5f * (dx * dx + dy * dy));
            float iou2 = iou * iou;
            float align = quality * (iou2 * iou2 * iou2) * prior;

            unsigned long long k =
                ((unsigned long long)__float_as_uint(align) << 32) |
                (unsigned long long)(0x7FFFFFFFu - (unsigned)p);
            if (k > lk[TOPK - 1]) {
                int q = TOPK - 1;
                while (q > 0 && lk[q - 1] < k) { lk[q] = lk[q - 1]; --q; }
                lk[q] = k;
            }
        }
    }

    // ---- tree merge in shared memory ----
    __shared__ unsigned long long sm[256 * TOPK];
#pragma unroll
    for (int j = 0; j < TOPK; j++) sm[tid * TOPK + j] = lk[j];
    __syncthreads();

    for (int stride = 128; stride > 0; stride >>= 1) {
        if (tid < stride) {
            unsigned long long* A = &sm[tid * TOPK];
            const unsigned long long* B = &sm[(tid + stride) * TOPK];
            unsigned long long outv[TOPK];
            int ia = 0, ib = 0;
#pragma unroll
            for (int j = 0; j < TOPK; j++) {
                unsigned long long av = (ia < TOPK) ? A[ia] : 0ull;
                unsigned long long bv = (ib < TOPK) ? B[ib] : 0ull;
                if (av >= bv) { outv[j] = av; ia++; }
                else          { outv[j] = bv; ib++; }
            }
#pragma unroll
            for (int j = 0; j < TOPK; j++) A[j] = outv[j];
        }
        __syncthreads();
    }

    // ---- scatter selected anchors (<=13) ----
    if (tid < TOPK) {
        unsigned long long k = sm[tid];
        if (k != 0ull) {
            unsigned p = 0x7FFFFFFFu - (unsigned)(k & 0xFFFFFFFFu);
            unsigned long long nk = (k & 0xFFFFFFFF00000000ull) |
                                    (unsigned long long)(0x7FFFFFFFu - (unsigned)g);
            atomicMax(&g_key[p], nk);
        }
    }
}

// ---------------------------------------------------------------------------
// Kernel 3: fused output writer — ONE warp per anchor row. Writes the whole
// target_scores row (zeros except matched label), plus boxes/fg/mgi/ml.
// Pure store pass over the entire 128 MB output; no prior zeroing needed.
// g_key==0 <=> background (selections always have nonzero low word).
// Output layout (float32, reference return order, flattened):
//   [0, P*C) target_scores | next 4P target_boxes | next P fg_mask
//   | next P matched_gt_indices | next P matched_labels
// ---------------------------------------------------------------------------
__global__ void __launch_bounds__(256) fused_out(
    const float* __restrict__ pboxes, const float* __restrict__ gboxes,
    float* __restrict__ out, int P, int C) {
    int warp = (blockIdx.x * blockDim.x + threadIdx.x) >> 5;
    int lane = threadIdx.x & 31;
    if (warp >= P) return;
    int p = warp;

    float* out_boxes = out + (size_t)P * C;
    float* out_fg = out_boxes + (size_t)P * 4;
    float* out_mgi = out_fg + P;
    float* out_ml = out_mgi + P;

    unsigned long long k = g_key[p];
    int label = -1;
    float score = 0.f;
    if (k != 0ull) {
        int g = (int)(0x7FFFFFFFu - (unsigned)(k & 0xFFFFFFFFu));
        float x0 = gboxes[4 * g + 0], y0 = gboxes[4 * g + 1];
        float x1 = gboxes[4 * g + 2], y1 = gboxes[4 * g + 3];
        float4 pb = ((const float4*)pboxes)[p];
        float ix0 = fmaxf(x0, pb.x), iy0 = fmaxf(y0, pb.y);
        float ix1 = fminf(x1, pb.z), iy1 = fminf(y1, pb.w);
        float inter = fmaxf(ix1 - ix0, 0.f) * fmaxf(iy1 - iy0, 0.f);
        float ag = fmaxf(x1 - x0, 0.f) * fmaxf(y1 - y0, 0.f);
        float ap = fmaxf(pb.z - pb.x, 0.f) * fmaxf(pb.w - pb.y, 0.f);
        float iou = inter / (ag + ap - inter + 1e-7f);
        label = g_labels[g];
        score = fmaxf(iou, 0.1f);
        if (lane == 0) {
            ((float4*)out_boxes)[p] = make_float4(x0, y0, x1, y1);
            out_fg[p] = 1.0f;
            out_mgi[p] = (float)g;
            out_ml[p] = (float)label;
        }
    } else if (lane == 0) {
        ((float4*)out_boxes)[p] = make_float4(0.f, 0.f, 0.f, 0.f);
        out_fg[p] = 0.f;
        out_mgi[p] = -1.f;
        out_ml[p] = -1.f;
    }

    float* row = out + (size_t)p * C;
    for (int j = lane; j < C; j += 32)
        row[j] = (j == label) ? score : 0.f;
}

// ---------------------------------------------------------------------------
extern "C" void kernel_launch(void* const* d_in, const int* in_sizes, int n_in,
                              void* d_out, int out_size) {
    const float* pred_scores = (const float*)d_in[0];
    const float* pred_boxes  = (const float*)d_in[1];
    const float* pred_obj    = (const float*)d_in[2];
    const float* anchors     = (const float*)d_in[3];
    const float* gt_boxes    = (const float*)d_in[4];
    const void*  gt_labels   = d_in[5];
    const unsigned char* vmask = (const unsigned char*)d_in[6];

    int P = in_sizes[2];            // pred_objectness count
    int C = in_sizes[0] / P;        // pred_scores is (P, C)
    int G = in_sizes[4] / 4;        // gt_boxes is (G, 4)

    decode_and_zerokey<<<336, 256>>>(gt_labels, vmask, anchors, P, G, C);
    topk_per_gt<<<G, 256>>>(pred_scores, pred_boxes, pred_obj, anchors, gt_boxes, P, C);
    int warps_needed = P;                      // one warp per anchor row
    int blocks = (warps_needed * 32 + 255) / 256;
    fused_out<<<blocks, 256>>>(pred_boxes, gt_boxes, (float*)d_out, P, C);
}